// round 16
// baseline (speedup 1.0000x reference)
#include <cuda_runtime.h>
#include <cuda_bf16.h>
#include <cuda_fp16.h>
#include <math.h>
#include <stdint.h>

#define B_ 32
#define T_ 512
#define D_ 1024
#define H_ 1024
#define ZN 4096
#define NBLK 128
#define NT2 512
#define RED_S 40

// ---------------- device scratch ----------------
__device__ unsigned g_xp[(size_t)T_ * 16384];   // 32MB: x (reversed time), fp16, mma-fragment packed per t
__device__ unsigned g_h16[2][16384];            // 128KB: double-buffered h, fp16, fragment packed
__device__ unsigned g_flags[NBLK * 32];         // per-block progress flags, 128B apart
__device__ unsigned g_done = 0;

// ---------------- helpers ----------------
__device__ __forceinline__ float sigf(float x) { return 1.0f / (1.0f + __expf(-x)); }

__device__ __forceinline__ uint32_t packh2(float a, float b) {
    __half2 h = __halves2half2(__float2half_rn(a), __float2half_rn(b));
    return *(uint32_t*)&h;
}

// fp16 mma m16n8k16, fp32 accumulate
__device__ __forceinline__ void mma_f16(float* c, const uint32_t* a, uint32_t b0, uint32_t b1) {
    asm volatile(
        "mma.sync.aligned.m16n8k16.row.col.f32.f16.f16.f32 "
        "{%0,%1,%2,%3}, {%4,%5,%6,%7}, {%8,%9}, {%0,%1,%2,%3};"
        : "+f"(c[0]), "+f"(c[1]), "+f"(c[2]), "+f"(c[3])
        : "r"(a[0]), "r"(a[1]), "r"(a[2]), "r"(a[3]), "r"(b0), "r"(b1));
}

__device__ __forceinline__ unsigned ld_acq(const unsigned* p) {
    unsigned v;
    asm volatile("ld.global.acquire.gpu.u32 %0, [%1];" : "=r"(v) : "l"(p) : "memory");
    return v;
}
__device__ __forceinline__ void st_rel(unsigned* p, unsigned v) {
    asm volatile("st.global.release.gpu.u32 [%0], %1;" :: "l"(p), "r"(v) : "memory");
}

// fragment word(b,k) for a 32x1024 fp16 operand (verified R12-R15):
// ((k>>4)*2 + (b>>4))*128 + ((b&7)*4 + ((k&7)>>1))*4 + ((k>>3)&1)*2 + ((b>>3)&1)

// ========== Repack x into per-t fragment layout: g_xp[t*16384 + word(b,k)] ==========
__global__ __launch_bounds__(256) void repack_x(const float* __restrict__ x) {
    const int t = blockIdx.x;            // processing order; source time T-1-t
    const int tid = threadIdx.x;
    const int b = tid >> 3;
    const int k0 = (tid & 7) * 128;

    const float* src = x + ((size_t)b * T_ + (size_t)(T_ - 1 - t)) * D_ + k0;
    unsigned* dst = g_xp + (size_t)t * 16384;
    const int bhi = ((b >> 4) & 1) * 128;
    const int bmid = (b & 7) * 16;
    const int blo = (b >> 3) & 1;

#pragma unroll 8
    for (int j = 0; j < 64; ++j) {
        int k = k0 + 2 * j;
        float2 v = *(const float2*)(src + 2 * j);
        int word = (k >> 4) * 256 + bhi + bmid + ((k & 7) >> 1) * 4 + ((k >> 3) & 1) * 2 + blo;
        dst[word] = packh2(v.x, v.y);
    }
}

// ---- accumulate NCH c16-chunks of one operand into acc ----
template <int NCH>
__device__ __forceinline__ void mma_part(float* acc /*[2][4][4] flat*/,
                                         const uint4* __restrict__ abase,
                                         const uint4* __restrict__ Wq,
                                         int c16base, int lane) {
#pragma unroll
    for (int kk = 0; kk < NCH; ++kk) {
        int c16 = c16base + kk;
        uint4 b0 = Wq[kk * 64 + lane];
        uint4 b1 = Wq[kk * 64 + 32 + lane];
        uint32_t a[2][4];
#pragma unroll
        for (int mt = 0; mt < 2; ++mt) {
            uint4 v = __ldcg(&abase[(c16 * 2 + mt) * 32 + lane]);
            a[mt][0] = v.x; a[mt][1] = v.y; a[mt][2] = v.z; a[mt][3] = v.w;
        }
#pragma unroll
        for (int mt = 0; mt < 2; ++mt) {
            mma_f16(acc + (mt * 4 + 0) * 4, a[mt], b0.x, b0.y);
            mma_f16(acc + (mt * 4 + 1) * 4, a[mt], b0.z, b0.w);
            mma_f16(acc + (mt * 4 + 2) * 4, a[mt], b1.x, b1.y);
            mma_f16(acc + (mt * 4 + 3) * 4, a[mt], b1.z, b1.w);
        }
    }
}

// ---- store warp's 32x32 partial into its red slab ----
__device__ __forceinline__ void sts_part(const float* acc, float* __restrict__ red,
                                         int wid, int g4, int l4) {
#pragma unroll
    for (int mt = 0; mt < 2; ++mt) {
#pragma unroll
        for (int nt = 0; nt < 4; ++nt) {
            const float* a = acc + (mt * 4 + nt) * 4;
            int row = mt * 16 + g4;
            int col = nt * 8 + 2 * l4;
            *(float2*)&red[wid * (32 * RED_S) + row * RED_S + col] = make_float2(a[0], a[1]);
            *(float2*)&red[wid * (32 * RED_S) + (row + 8) * RED_S + col] = make_float2(a[2], a[3]);
        }
    }
}

// ============ Fused persistent LSTM, role-swapped asymmetric split ===========
// Warps 0-7 (x-warps): x rows [w*128,+128) computed BEFORE sync#1 (concurrent with
// gates), plus h rows [1024+w*64,+64) after the poll.
// Warps 8-15 (gate warps): gates/h-store/out (tid-256 -> (pb,pn)), plus h rows
// [1024+w*64,+64) only. Post-sync chain for all: poll -> h-mma(64k) -> STS.
__global__ __launch_bounds__(NT2, 1) void lstm_fused(const float* __restrict__ Wfull,
                                                     const float* __restrict__ bias,
                                                     float* __restrict__ out) {
    extern __shared__ uint32_t dynsmem[];
    uint32_t* W_s = dynsmem;        // [0,16384): x slabs, 8 x 2048 words; [16384,32768): h slabs, 16 x 1024
    float* red = (float*)(dynsmem + 32768);   // 16 * 32 * 40 floats = 80KB

    const int tid = threadIdx.x;
    const int wid = tid >> 5, lane = tid & 31;
    const int l4 = lane & 3, g4 = lane >> 2;
    const int bid = blockIdx.x;
    const int n0 = bid * 8;
    const bool gate_role = tid >= 256;        // warps 8-15
    const int gt = tid - 256;
    const int pb = (gt >> 3) & 31;
    const int pn = gt & 7;

    // pointwise h-store address: element (b=pb, k=n0+pn), fragment layout
    const int hword = ((bid >> 1) * 2 + (pb >> 4)) * 128 + ((pb & 7) * 4 + (pn >> 1)) * 4 +
                      (bid & 1) * 2 + ((pb >> 3) & 1);
    const int hbyte = hword * 4 + (pn & 1) * 2;

    // ---- pack concat-W into SMEM ----
    // x region (words [0,16384)): slab w (0..7) = x rows [w*128, +128)
    // h region (words [16384,32768)): slab w (0..15) = h rows [1024+w*64, +64)
    for (int widx = tid; widx < 32768; widx += NT2) {
        int k, rem;
        if (widx < 16384) {
            int w = widx >> 11; rem = widx & 2047;
            int kk = rem >> 8;
            int hi = rem & 1, l4w = (rem >> 2) & 3;
            k = w * 128 + kk * 16 + hi * 8 + l4w * 2;
        } else {
            int idx2 = widx - 16384;
            int w = idx2 >> 10; rem = idx2 & 1023;
            int kk = rem >> 8;
            int hi = rem & 1, l4w = (rem >> 2) & 3;
            k = 1024 + w * 64 + kk * 16 + hi * 8 + l4w * 2;
        }
        int q128 = (rem >> 7) & 1;
        int nt = q128 * 2 + ((rem & 3) >> 1);
        int g4c = (rem >> 4) & 7;
        int col = nt * H_ + n0 + g4c;
        W_s[widx] = packh2(__ldg(Wfull + (size_t)k * ZN + col),
                           __ldg(Wfull + (size_t)(k + 1) * ZN + col));
    }

    float bz[4];
    if (gate_role) {
#pragma unroll
        for (int g = 0; g < 4; ++g) bz[g] = __ldg(bias + g * H_ + n0 + pn);
    }
    __syncthreads();

    const uint4* Wqx = (const uint4*)W_s + (size_t)wid * 512;             // x slab (wid<8)
    const uint4* Wqh = (const uint4*)W_s + 4096 + (size_t)wid * 256;      // h slab
    const int c16bx = wid * 8;   // x chunk base (wid<8)
    const int c16bh = wid * 4;   // h chunk base
    float c_reg = 0.0f;

    // ---- prologue: partials for step 0 (h = 0) ----
    if (!gate_role) {
        float acc[32];
#pragma unroll
        for (int e = 0; e < 32; ++e) acc[e] = 0.0f;
        mma_part<8>(acc, (const uint4*)g_xp, Wqx, c16bx, lane);
        sts_part(acc, red, wid, g4, l4);
    } else {
        for (int i = lane; i < 32 * RED_S; i += 32) red[wid * (32 * RED_S) + i] = 0.0f;
    }
    __syncthreads();

    for (int t = 0; t < T_ - 1; ++t) {
        float acc[32];
#pragma unroll
        for (int e = 0; e < 32; ++e) acc[e] = 0.0f;

        if (gate_role) {
            // ---- gates for step t ----
            float z[4];
#pragma unroll
            for (int g = 0; g < 4; ++g) {
                float s = bz[g];
#pragma unroll
                for (int w = 0; w < 16; ++w)
                    s += red[w * (32 * RED_S) + pb * RED_S + g * 8 + pn];
                z[g] = s;
            }
            c_reg = sigf(z[2] + 1.0f) * c_reg + sigf(z[0]) * tanhf(z[1]);
            float hv = sigf(z[3]) * tanhf(c_reg);
            unsigned short hs = __half_as_ushort(__float2half_rn(hv));
            asm volatile("st.global.cg.u16 [%0], %1;"
                         :: "l"((char*)g_h16[(t + 1) & 1] + hbyte), "h"(hs) : "memory");
        } else {
            // ---- x projection for step t+1, concurrent with gates ----
            mma_part<8>(acc, (const uint4*)(g_xp + (size_t)(t + 1) * 16384), Wqx, c16bx, lane);
        }
        __syncthreads();                       // sync#1: h(t+1) stores + red reads done
        if (tid == 0) st_rel(&g_flags[bid * 32], (unsigned)(t + 1));
        if (gate_role)
            __stcs(&out[(size_t)pb * (T_ * H_) + (size_t)t * H_ + n0 + pn], c_reg);

        // ---- poll own 8 producers for h(t+1), then h-mma + STS ----
        if (lane < 8) {
            const unsigned* fp = &g_flags[(wid * 8 + lane) * 32];
            while (ld_acq(fp) < (unsigned)(t + 1)) { }
        }
        __syncwarp();
        mma_part<4>(acc, (const uint4*)g_h16[(t + 1) & 1], Wqh, c16bh, lane);
        sts_part(acc, red, wid, g4, l4);
        __syncthreads();                       // sync#2: partials for t+1 visible
    }

    // ---- epilogue: gates for step T-1 ----
    if (gate_role) {
        float z[4];
#pragma unroll
        for (int g = 0; g < 4; ++g) {
            float s = bz[g];
#pragma unroll
            for (int w = 0; w < 16; ++w)
                s += red[w * (32 * RED_S) + pb * RED_S + g * 8 + pn];
            z[g] = s;
        }
        c_reg = sigf(z[2] + 1.0f) * c_reg + sigf(z[0]) * tanhf(z[1]);
        __stcs(&out[(size_t)pb * (T_ * H_) + (size_t)(T_ - 1) * H_ + n0 + pn], c_reg);
    }

    // ---- reset flags for deterministic graph replay ----
    __syncthreads();
    if (tid == 0) atomicAdd(&g_done, 1u);
    if (bid == 0) {
        if (tid == 0) {
            while (*(volatile unsigned*)&g_done < (unsigned)NBLK) { }
        }
        __syncthreads();
        if (tid < NBLK) g_flags[tid * 32] = 0u;
        __syncthreads();
        if (tid == 0) { __threadfence(); g_done = 0u; }
    }
}

// ---------------- launch ----------------
extern "C" void kernel_launch(void* const* d_in, const int* in_sizes, int n_in,
                              void* d_out, int out_size) {
    (void)in_sizes; (void)n_in; (void)out_size;
    const float* x    = (const float*)d_in[0];
    const float* kern = (const float*)d_in[2];
    const float* bias = (const float*)d_in[3];
    float* out = (float*)d_out;

    const int smem2 = (32768 + 16 * 32 * RED_S) * 4;   // 212992 B
    cudaFuncSetAttribute(lstm_fused, cudaFuncAttributeMaxDynamicSharedMemorySize, smem2);

    repack_x<<<T_, 256>>>(x);
    lstm_fused<<<NBLK, NT2, smem2>>>(kern, bias, out);
}

// round 17
// speedup vs baseline: 1.3410x; 1.3410x over previous
#include <cuda_runtime.h>
#include <cuda_bf16.h>
#include <cuda_fp16.h>
#include <math.h>
#include <stdint.h>

#define B_ 32
#define T_ 512
#define D_ 1024
#define H_ 1024
#define ZN 4096
#define NBLK 128
#define NT2 512
#define RED_S 40

// ---------------- device scratch ----------------
__device__ unsigned g_xp[(size_t)T_ * 16384];   // 32MB: x (reversed time), fp16, mma-fragment packed per t
__device__ unsigned g_h16[2][16384];            // 128KB: double-buffered h, fp16, fragment packed
__device__ unsigned g_flags[NBLK * 32];         // per-block progress flags, 128B apart
__device__ unsigned g_done = 0;

// ---------------- helpers ----------------
__device__ __forceinline__ float sigf(float x) { return 1.0f / (1.0f + __expf(-x)); }

__device__ __forceinline__ uint32_t packh2(float a, float b) {
    __half2 h = __halves2half2(__float2half_rn(a), __float2half_rn(b));
    return *(uint32_t*)&h;
}

// fp16 mma m16n8k16, fp32 accumulate
__device__ __forceinline__ void mma_f16(float* c, const uint32_t* a, uint32_t b0, uint32_t b1) {
    asm volatile(
        "mma.sync.aligned.m16n8k16.row.col.f32.f16.f16.f32 "
        "{%0,%1,%2,%3}, {%4,%5,%6,%7}, {%8,%9}, {%0,%1,%2,%3};"
        : "+f"(c[0]), "+f"(c[1]), "+f"(c[2]), "+f"(c[3])
        : "r"(a[0]), "r"(a[1]), "r"(a[2]), "r"(a[3]), "r"(b0), "r"(b1));
}

__device__ __forceinline__ unsigned ld_acq(const unsigned* p) {
    unsigned v;
    asm volatile("ld.global.acquire.gpu.u32 %0, [%1];" : "=r"(v) : "l"(p) : "memory");
    return v;
}
__device__ __forceinline__ void st_rel(unsigned* p, unsigned v) {
    asm volatile("st.global.release.gpu.u32 [%0], %1;" :: "l"(p), "r"(v) : "memory");
}

// fragment word(b,k) for a 32x1024 fp16 operand (verified R12-R15):
// ((k>>4)*2 + (b>>4))*128 + ((b&7)*4 + ((k&7)>>1))*4 + ((k>>3)&1)*2 + ((b>>3)&1)

// ========== Repack x into per-t fragment layout: g_xp[t*16384 + word(b,k)] ==========
__global__ __launch_bounds__(256) void repack_x(const float* __restrict__ x) {
    const int t = blockIdx.x;            // processing order; source time T-1-t
    const int tid = threadIdx.x;
    const int b = tid >> 3;
    const int k0 = (tid & 7) * 128;

    const float* src = x + ((size_t)b * T_ + (size_t)(T_ - 1 - t)) * D_ + k0;
    unsigned* dst = g_xp + (size_t)t * 16384;
    const int bhi = ((b >> 4) & 1) * 128;
    const int bmid = (b & 7) * 16;
    const int blo = (b >> 3) & 1;

#pragma unroll 8
    for (int j = 0; j < 64; ++j) {
        int k = k0 + 2 * j;
        float2 v = *(const float2*)(src + 2 * j);
        int word = (k >> 4) * 256 + bhi + bmid + ((k & 7) >> 1) * 4 + ((k >> 3) & 1) * 2 + blo;
        dst[word] = packh2(v.x, v.y);
    }
}

// ---- accumulate one 64-k operand slice into acc (4 c16 chunks, R12/R15 shape) ----
__device__ __forceinline__ void mma_part(float* acc /*[2][4][4] flat*/,
                                         const uint4* __restrict__ abase,
                                         const uint4* __restrict__ Wq,
                                         int c16base, int lane) {
#pragma unroll
    for (int kk = 0; kk < 4; ++kk) {
        int c16 = c16base + kk;
        uint4 b0 = Wq[kk * 64 + lane];
        uint4 b1 = Wq[kk * 64 + 32 + lane];
        uint32_t a[2][4];
#pragma unroll
        for (int mt = 0; mt < 2; ++mt) {
            uint4 v = __ldcg(&abase[(c16 * 2 + mt) * 32 + lane]);
            a[mt][0] = v.x; a[mt][1] = v.y; a[mt][2] = v.z; a[mt][3] = v.w;
        }
#pragma unroll
        for (int mt = 0; mt < 2; ++mt) {
            mma_f16(acc + (mt * 4 + 0) * 4, a[mt], b0.x, b0.y);
            mma_f16(acc + (mt * 4 + 1) * 4, a[mt], b0.z, b0.w);
            mma_f16(acc + (mt * 4 + 2) * 4, a[mt], b1.x, b1.y);
            mma_f16(acc + (mt * 4 + 3) * 4, a[mt], b1.z, b1.w);
        }
    }
}

// ---- store warp's 32x32 partial into its red slab ----
__device__ __forceinline__ void sts_part(const float* acc, float* __restrict__ red,
                                         int wid, int g4, int l4) {
#pragma unroll
    for (int mt = 0; mt < 2; ++mt) {
#pragma unroll
        for (int nt = 0; nt < 4; ++nt) {
            const float* a = acc + (mt * 4 + nt) * 4;
            int row = mt * 16 + g4;
            int col = nt * 8 + 2 * l4;
            *(float2*)&red[wid * (32 * RED_S) + row * RED_S + col] = make_float2(a[0], a[1]);
            *(float2*)&red[wid * (32 * RED_S) + (row + 8) * RED_S + col] = make_float2(a[2], a[3]);
        }
    }
}

// ============ Fused persistent LSTM: accumulator-level fusion (R15) + x L2 prefetch ========
// All 16 warps symmetric. Warp w owns concat-K rows x:[w*64,+64) AND h:[1024+w*64,+64).
// acc = x-part(t+1) + h-part(t+1) after poll; one STS; 16-way reduce by tid<256.
// Each warp prefetches its 4KB x-slice of step t+2 into L2 right after the STS.
__global__ __launch_bounds__(NT2, 1) void lstm_fused(const float* __restrict__ Wfull,
                                                     const float* __restrict__ bias,
                                                     float* __restrict__ out) {
    extern __shared__ uint32_t dynsmem[];
    uint32_t* W_s = dynsmem;                          // 16 warps * 2048 words = 128KB
    float* red = (float*)(dynsmem + 32768);           // 16 * 32 * 40 floats = 80KB

    const int tid = threadIdx.x;
    const int wid = tid >> 5, lane = tid & 31;
    const int l4 = lane & 3, g4 = lane >> 2;
    const int bid = blockIdx.x;
    const int n0 = bid * 8;
    const int pb = (tid >> 3) & 31;
    const int pn = tid & 7;
    const bool active = tid < 256;

    // pointwise h-store address: element (b=pb, k=n0+pn), fragment layout
    const int hword = ((bid >> 1) * 2 + (pb >> 4)) * 128 + ((pb & 7) * 4 + (pn >> 1)) * 4 +
                      (bid & 1) * 2 + ((pb >> 3) & 1);
    const int hbyte = hword * 4 + (pn & 1) * 2;

    // ---- pack concat-W into SMEM: warp slab = [x sub-slab 1024w | h sub-slab 1024w] ----
    for (int widx = tid; widx < 32768; widx += NT2) {
        int w = widx >> 11, rem = widx & 2047;
        int s = rem >> 10, rem2 = rem & 1023;
        int kk = rem2 >> 8, q128 = (rem2 >> 7) & 1;
        int lw = (rem2 >> 2) & 31, low2 = rem2 & 3;
        int nt = q128 * 2 + (low2 >> 1), hi = low2 & 1;
        int g4c = lw >> 2, l4w = lw & 3;
        int k = s * 1024 + w * 64 + kk * 16 + hi * 8 + l4w * 2;   // concat row
        int col = nt * H_ + n0 + g4c;
        W_s[widx] = packh2(__ldg(Wfull + (size_t)k * ZN + col),
                           __ldg(Wfull + (size_t)(k + 1) * ZN + col));
    }

    float bz[4];
    if (active) {
#pragma unroll
        for (int g = 0; g < 4; ++g) bz[g] = __ldg(bias + g * H_ + n0 + pn);
    }
    __syncthreads();

    const uint4* Wqx = (const uint4*)W_s + (size_t)wid * 512;   // x sub-slab
    const uint4* Wqh = Wqx + 256;                                // h sub-slab
    const int c16b = wid * 4;
    float c_reg = 0.0f;

    // warp's contiguous 4KB x-slice starts at word offset wid*1024 within a step's 16384
    const char* xslice0 = (const char*)(g_xp + (size_t)wid * 1024) + lane * 128;

    // ---- prologue: partials for step 0 (h = 0 -> x part only); prefetch x(1) ----
    {
        asm volatile("prefetch.global.L2 [%0];" :: "l"(xslice0 + (size_t)1 * 65536));
        float acc[32];
#pragma unroll
        for (int e = 0; e < 32; ++e) acc[e] = 0.0f;
        mma_part(acc, (const uint4*)g_xp, Wqx, c16b, lane);
        sts_part(acc, red, wid, g4, l4);
    }
    __syncthreads();

    for (int t = 0; t < T_ - 1; ++t) {
        // ---- gates for step t ----
        if (active) {
            float z[4];
#pragma unroll
            for (int g = 0; g < 4; ++g) {
                float s = bz[g];
#pragma unroll
                for (int w = 0; w < 16; ++w)
                    s += red[w * (32 * RED_S) + pb * RED_S + g * 8 + pn];
                z[g] = s;
            }
            c_reg = sigf(z[2] + 1.0f) * c_reg + sigf(z[0]) * tanhf(z[1]);
            float hv = sigf(z[3]) * tanhf(c_reg);
            unsigned short hs = __half_as_ushort(__float2half_rn(hv));
            asm volatile("st.global.cg.u16 [%0], %1;"
                         :: "l"((char*)g_h16[(t + 1) & 1] + hbyte), "h"(hs) : "memory");
        }
        __syncthreads();                       // h(t+1) stores done, red reads done
        if (tid == 0) st_rel(&g_flags[bid * 32], (unsigned)(t + 1));
        if (active) __stcs(&out[(size_t)pb * (T_ * H_) + (size_t)t * H_ + n0 + pn], c_reg);

        // ---- partials for step t+1: x-part (L2-hot), poll, h-part ----
        float acc[32];
#pragma unroll
        for (int e = 0; e < 32; ++e) acc[e] = 0.0f;
        mma_part(acc, (const uint4*)(g_xp + (size_t)(t + 1) * 16384), Wqx, c16b, lane);

        if (lane < 8) {
            const unsigned* fp = &g_flags[(wid * 8 + lane) * 32];
            while (ld_acq(fp) < (unsigned)(t + 1)) { }
        }
        __syncwarp();
        mma_part(acc, (const uint4*)g_h16[(t + 1) & 1], Wqh, c16b, lane);
        sts_part(acc, red, wid, g4, l4);

        // ---- prefetch this warp's x-slice for step t+2 (off-chain) ----
        if (t + 2 < T_)
            asm volatile("prefetch.global.L2 [%0];"
                         :: "l"(xslice0 + (size_t)(t + 2) * 65536));

        __syncthreads();                       // partials for t+1 visible
    }

    // ---- epilogue: gates for step T-1 ----
    if (active) {
        float z[4];
#pragma unroll
        for (int g = 0; g < 4; ++g) {
            float s = bz[g];
#pragma unroll
            for (int w = 0; w < 16; ++w)
                s += red[w * (32 * RED_S) + pb * RED_S + g * 8 + pn];
            z[g] = s;
        }
        c_reg = sigf(z[2] + 1.0f) * c_reg + sigf(z[0]) * tanhf(z[1]);
        __stcs(&out[(size_t)pb * (T_ * H_) + (size_t)(T_ - 1) * H_ + n0 + pn], c_reg);
    }

    // ---- reset flags for deterministic graph replay ----
    __syncthreads();
    if (tid == 0) atomicAdd(&g_done, 1u);
    if (bid == 0) {
        if (tid == 0) {
            while (*(volatile unsigned*)&g_done < (unsigned)NBLK) { }
        }
        __syncthreads();
        if (tid < NBLK) g_flags[tid * 32] = 0u;
        __syncthreads();
        if (tid == 0) { __threadfence(); g_done = 0u; }
    }
}

// ---------------- launch ----------------
extern "C" void kernel_launch(void* const* d_in, const int* in_sizes, int n_in,
                              void* d_out, int out_size) {
    (void)in_sizes; (void)n_in; (void)out_size;
    const float* x    = (const float*)d_in[0];
    const float* kern = (const float*)d_in[2];
    const float* bias = (const float*)d_in[3];
    float* out = (float*)d_out;

    const int smem2 = (32768 + 16 * 32 * RED_S) * 4;   // 212992 B
    cudaFuncSetAttribute(lstm_fused, cudaFuncAttributeMaxDynamicSharedMemorySize, smem2);

    repack_x<<<T_, 256>>>(x);
    lstm_fused<<<NBLK, NT2, smem2>>>(kern, bias, out);
}